// round 14
// baseline (speedup 1.0000x reference)
#include <cuda_runtime.h>

// Problem constants
#define B_   32
#define C_   2048
#define D_   16
#define M_   784           // 28*28
#define CHUNK  256
#define NCHUNK (C_/CHUNK)  // 8
#define NPAIR 136
#define EPS  1e-5f

// ---------------- scratch (device globals; no allocations) ----------------
__device__ float g_Y[B_ * D_ * M_];     // conv output (atomic-accumulated, 1.6 MB)
__device__ float g_rs1[B_ * D_];        // per-(b,d) row sum
__device__ float g_rs2[B_ * D_];        // per-(b,d) row sum of squares
__device__ float g_S[B_ * NPAIR];       // pair product sums (atomic)
__device__ float g_mean[B_ * D_];       // per-(b,d) spatial sums (atomic)
__device__ float g_r[B_ * 64];          // row-conv output

// packed f32x2 FMA (Blackwell)
__device__ __forceinline__ void fma2(unsigned long long &acc,
                                     unsigned long long a,
                                     unsigned long long b) {
    asm("fma.rn.f32x2 %0, %1, %2, %0;" : "+l"(acc) : "l"(a), "l"(b));
}

// ---------------- kZ: zero accumulators ----------------
__global__ void kZ() {
    const int tid = blockIdx.x * blockDim.x + threadIdx.x;
    float4* y4 = reinterpret_cast<float4*>(g_Y);
    if (tid < B_ * D_ * M_ / 4) y4[tid] = make_float4(0.f, 0.f, 0.f, 0.f);
    if (tid < B_ * NPAIR) g_S[tid] = 0.f;
    if (tid < B_ * D_)    g_mean[tid] = 0.f;
}

// ---------------- kA: y[b,d,m] += sum_{c in chunk} w[d,c]*x[b,c,m] ---------
// grid = 32 b x 8 chunks x 2 m-halves = 512 blocks, 224 threads.
// m=2 per thread -> ~55 regs -> 5 blocks/SM (~35 warps) for latency hiding.
__global__ __launch_bounds__(224) void kA(const float* __restrict__ x,
                                          const float* __restrict__ w) {
    __shared__ __align__(16) float2 sw[CHUNK][D_];  // (w,w) pairs, 32KB

    const int bx   = blockIdx.x;
    const int b    = bx >> 4;
    const int ch   = (bx >> 1) & 7;
    const int half = bx & 1;
    const int c0   = ch * CHUNK;
    const int tid  = threadIdx.x;

    // stage W chunk, duplicated into float2 halves
    for (int i = tid; i < CHUNK * D_; i += 224) {
        int c = i >> 4, d = i & 15;
        float wv = w[d * C_ + c0 + c];
        sw[c][d] = make_float2(wv, wv);
    }
    __syncthreads();

    if (tid >= 196) return;             // 196*2 = 392 m per half
    const int m0 = half * 392 + tid * 2;
    const float* xb = x + ((size_t)b * C_ + c0) * M_ + m0;

    unsigned long long acc[D_];
#pragma unroll
    for (int d = 0; d < D_; d++) acc[d] = 0ull;

    for (int c = 0; c < CHUNK; c += 4) {
        unsigned long long xv[4];
#pragma unroll
        for (int u = 0; u < 4; u++)
            xv[u] = *reinterpret_cast<const unsigned long long*>(
                        xb + (size_t)(c + u) * M_);
#pragma unroll
        for (int u = 0; u < 4; u++) {
            const ulonglong2* wp =
                reinterpret_cast<const ulonglong2*>(&sw[c + u][0]);
#pragma unroll
            for (int q = 0; q < 8; q++) {
                ulonglong2 w2 = wp[q];
                fma2(acc[2 * q],     xv[u], w2.x);
                fma2(acc[2 * q + 1], xv[u], w2.y);
            }
        }
    }

    float* yb = g_Y + ((size_t)b * D_) * M_ + m0;
#pragma unroll
    for (int d = 0; d < D_; d++) {
        float lo = __uint_as_float((unsigned int)(acc[d] & 0xffffffffull));
        float hi = __uint_as_float((unsigned int)(acc[d] >> 32));
        atomicAdd(yb + d * M_ + 0, lo);
        atomicAdd(yb + d * M_ + 1, hi);
    }
}

// ---------------- kB: per-(b,d) row sums from g_Y (L2-hot, 1.6 MB) ---------
// grid = 128 blocks, 128 threads; warp w of block bid owns row bid*4+w
__global__ void kB(void) {
    const int tid = threadIdx.x;
    const int wid = tid >> 5, lane = tid & 31;
    const int row = blockIdx.x * 4 + wid;

    const float4* r4 = reinterpret_cast<const float4*>(g_Y) + row * (M_ / 4);
    float s = 0.f, s2 = 0.f;
    for (int m = lane; m < M_ / 4; m += 32) {
        float4 v = r4[m];
        s  += v.x + v.y + v.z + v.w;
        s2 += v.x * v.x + v.y * v.y + v.z * v.z + v.w * v.w;
    }
    for (int o = 16; o; o >>= 1) {
        s  += __shfl_xor_sync(~0u, s,  o);
        s2 += __shfl_xor_sync(~0u, s2, o);
    }
    if (!lane) { g_rs1[row] = s; g_rs2[row] = s2; }
}

// ---------------- kC: BN+ReLU -> partial pair sums (quarter of m) ----------
// grid = 32*4 blocks (b, m-quarter of 196), 288 threads
__global__ __launch_bounds__(288) void kC(const float* __restrict__ g1,
                                          const float* __restrict__ b1) {
    __shared__ float sS[D_], sB[D_];
    __shared__ __align__(16) float ys[D_][196];   // 12.25 KB

    const int b = blockIdx.x >> 2, qtr = blockIdx.x & 3;
    const int tid = threadIdx.x;
    const int wid = tid >> 5, lane = tid & 31;

    // BN1 coefficients (redundant per block; reads 4KB of L2-hot sums)
    if (tid < D_) {
        float s = 0.f, s2 = 0.f;
#pragma unroll
        for (int bb = 0; bb < B_; bb++) {
            s  += g_rs1[bb * D_ + tid];
            s2 += g_rs2[bb * D_ + tid];
        }
        const float inv = 1.0f / (float)(B_ * M_);
        float mu  = s * inv;
        float var = s2 * inv - mu * mu;
        float sc  = g1[tid] * rsqrtf(var + EPS);
        sS[tid] = sc;
        sB[tid] = fmaf(-mu, sc, b1[tid]);
    }
    __syncthreads();

    // stage: ys[d][0..195] = relu(bn(g_Y)) for this m-quarter (L2-hot)
    const int m4base = qtr * 49;           // float4 offset within row
    for (int idx = tid; idx < D_ * 49; idx += 288) {
        int d = idx / 49, m4 = idx % 49;
        float4 v = reinterpret_cast<const float4*>(g_Y)
                       [(b * D_ + d) * (M_ / 4) + m4base + m4];
        float sc = sS[d], bs = sB[d];
        v.x = fmaxf(fmaf(v.x, sc, bs), 0.f);
        v.y = fmaxf(fmaf(v.y, sc, bs), 0.f);
        v.z = fmaxf(fmaf(v.z, sc, bs), 0.f);
        v.w = fmaxf(fmaf(v.w, sc, bs), 0.f);
        *reinterpret_cast<float4*>(&ys[d][m4 * 4]) = v;
    }
    __syncthreads();

    // partial row sums
    for (int r = wid; r < D_; r += 9) {
        float s = 0.f;
        for (int m = lane; m < 196; m += 32) s += ys[r][m];
        for (int o = 16; o; o >>= 1) s += __shfl_xor_sync(~0u, s, o);
        if (!lane) atomicAdd(&g_mean[b * D_ + r], s);
    }

    // pair partial products: thread t -> pair t>>1, half t&1 (98 m)
    {
        int p = tid >> 1;
        bool valid = (p < NPAIR);
        int pc = valid ? p : NPAIR - 1;
        int pi = 0, rem = pc;
        while (rem >= D_ - pi) { rem -= D_ - pi; pi++; }
        int pj = pi + rem;
        int h = tid & 1;
        const float2* ri = reinterpret_cast<const float2*>(&ys[pi][h * 98]);
        const float2* rj = reinterpret_cast<const float2*>(&ys[pj][h * 98]);
        float pacc = 0.f;
#pragma unroll 7
        for (int m = 0; m < 49; m++) {
            float2 a = ri[m], c = rj[m];
            pacc = fmaf(a.x, c.x, pacc);
            pacc = fmaf(a.y, c.y, pacc);
        }
        pacc += __shfl_xor_sync(~0u, pacc, 1);
        if (valid && h == 0) atomicAdd(&g_S[b * NPAIR + p], pacc);
    }
}

// ---------------- kD: finalize cov + row-BN + row-conv -> g_r --------------
// 1 block, 512 threads (16 warps), latency-optimized
__global__ __launch_bounds__(512) void kD(const float* __restrict__ g2,
                                          const float* __restrict__ b2,
                                          const float* __restrict__ w_row) {
    __shared__ float zc[D_ * D_ * 33];     // [i][j][b'] padded, 33.8 KB
    __shared__ float smu[B_ * D_];
    __shared__ unsigned char spi[NPAIR + 4], spj[NPAIR + 4];
    __shared__ float mu2[D_], rst[D_];

    const int tid = threadIdx.x;
    const int wid = tid >> 5, lane = tid & 31;

    // pair table (decode once)
    if (tid < NPAIR) {
        int pi = 0, rem = tid;
        while (rem >= D_ - pi) { rem -= D_ - pi; pi++; }
        spi[tid] = (unsigned char)pi;
        spj[tid] = (unsigned char)(pi + rem);
    }
    if (tid < B_ * D_) smu[tid] = g_mean[tid] * (1.0f / (float)M_);
    __syncthreads();

    // finalize cov: warp w handles batches w and w+16.
    // 34 float4 groups of pairs (136/4); lanes stride so ALL groups covered.
#pragma unroll
    for (int half = 0; half < 2; half++) {
        const int bb = wid + half * 16;
        for (int gidx = lane; gidx < 34; gidx += 32) {
            float4 sv = *reinterpret_cast<const float4*>(g_S + bb * NPAIR + gidx * 4);
            float vals[4] = {sv.x, sv.y, sv.z, sv.w};
#pragma unroll
            for (int u = 0; u < 4; u++) {
                int p = gidx * 4 + u;
                int pi = spi[p], pj = spj[p];
                float cv = vals[u] * (1.0f / (float)M_)
                         - smu[bb * D_ + pi] * smu[bb * D_ + pj];
                zc[(pi * D_ + pj) * 33 + bb] = cv;
                if (pi != pj) zc[(pj * D_ + pi) * 33 + bb] = cv;
            }
        }
    }
    __syncthreads();

    // row-BN stats: warp wid owns row i = wid, reduce over (b'=lane, j)
    {
        const int i = wid;
        float s = 0.f, s2 = 0.f;
#pragma unroll
        for (int j = 0; j < D_; j++) {
            float v = zc[(i * D_ + j) * 33 + lane];
            s += v; s2 += v * v;
        }
        for (int o = 16; o; o >>= 1) {
            s  += __shfl_xor_sync(~0u, s,  o);
            s2 += __shfl_xor_sync(~0u, s2, o);
        }
        if (!lane) {
            float m   = s * (1.0f / 512.0f);
            float var = s2 * (1.0f / 512.0f) - m * m;
            mu2[i] = m;
            rst[i] = rsqrtf(var + EPS);
        }
    }
    __syncthreads();

    // grouped row conv: 2048 outputs, 4 per thread
#pragma unroll
    for (int t = tid; t < B_ * 64; t += 512) {
        int b = t >> 6, o = t & 63, g = o >> 2;
        float mg = mu2[g];
        float rg = rst[g] * g2[g];
        float bg = b2[g];
        const float* wr = w_row + o * D_;
        float a = 0.f;
#pragma unroll
        for (int h = 0; h < D_; h++) {
            float z = fmaf(zc[(g * D_ + h) * 33 + b] - mg, rg, bg);
            a = fmaf(wr[h], z, a);
        }
        g_r[t] = a;
    }
}

// ---------------- kE: FC (2048x64) + sigmoid ----------------
// grid = 32*8 blocks, 256 threads; thread -> one output channel
__global__ __launch_bounds__(256) void kE(const float* __restrict__ w_fc,
                                          float* __restrict__ out) {
    __shared__ float rs[64];
    const int b = blockIdx.x >> 3, seg = blockIdx.x & 7, tid = threadIdx.x;
    if (tid < 64) rs[tid] = g_r[b * 64 + tid];
    __syncthreads();
    const int o = seg * 256 + tid;
    const float4* wp = reinterpret_cast<const float4*>(w_fc + (size_t)o * 64);
    float acc = 0.f;
#pragma unroll
    for (int t = 0; t < 16; t++) {
        float4 wv = wp[t];
        acc += wv.x * rs[4 * t] + wv.y * rs[4 * t + 1]
             + wv.z * rs[4 * t + 2] + wv.w * rs[4 * t + 3];
    }
    out[b * C_ + o] = 1.0f / (1.0f + __expf(-acc));
}

// ---------------- launch ----------------
extern "C" void kernel_launch(void* const* d_in, const int* in_sizes, int n_in,
                              void* d_out, int out_size) {
    const float* x      = (const float*)d_in[0];
    const float* w_conv = (const float*)d_in[1];
    const float* g1     = (const float*)d_in[2];
    const float* b1     = (const float*)d_in[3];
    const float* g2     = (const float*)d_in[4];
    const float* b2     = (const float*)d_in[5];
    const float* w_row  = (const float*)d_in[6];
    const float* w_fc   = (const float*)d_in[7];
    float* out = (float*)d_out;

    kZ<<<(B_ * D_ * M_ / 4 + 255) / 256, 256>>>();
    kA<<<B_ * NCHUNK * 2, 224>>>(x, w_conv);
    kB<<<B_ * D_ / 4, 128>>>();
    kC<<<B_ * 4, 288>>>(g1, b1);
    kD<<<1, 512>>>(g2, b2, w_row);
    kE<<<B_ * 8, 256>>>(w_fc, out);
}

// round 16
// speedup vs baseline: 1.3070x; 1.3070x over previous
#include <cuda_runtime.h>

// Problem constants
#define B_   32
#define C_   2048
#define D_   16
#define M_   784           // 28*28
#define CHUNK  256
#define NCHUNK (C_/CHUNK)  // 8
#define NPAIR 136
#define EPS  1e-5f

// ---------------- scratch (device globals; no allocations) ----------------
__device__ float g_Y[B_ * D_ * M_];     // conv output (atomic-accumulated, 1.6 MB)
__device__ float g_rs1[B_ * D_];        // per-(b,d) row sum
__device__ float g_rs2[B_ * D_];        // per-(b,d) row sum of squares
__device__ float g_S[B_ * NPAIR];       // pair product sums (atomic)
__device__ float g_mean[B_ * D_];       // per-(b,d) spatial sums (atomic)
__device__ float g_r[B_ * 64];          // row-conv output

// packed f32x2 FMA (Blackwell)
__device__ __forceinline__ void fma2(unsigned long long &acc,
                                     unsigned long long a,
                                     unsigned long long b) {
    asm("fma.rn.f32x2 %0, %1, %2, %0;" : "+l"(acc) : "l"(a), "l"(b));
}
// duplicate a float into both lanes of a packed f32x2 register
__device__ __forceinline__ unsigned long long dup2(float v) {
    unsigned long long r;
    asm("mov.b64 %0, {%1, %1};" : "=l"(r) : "f"(v));
    return r;
}

// ---------------- kZ: zero accumulators ----------------
__global__ void kZ() {
    const int tid = blockIdx.x * blockDim.x + threadIdx.x;
    float4* y4 = reinterpret_cast<float4*>(g_Y);
    if (tid < B_ * D_ * M_ / 4) y4[tid] = make_float4(0.f, 0.f, 0.f, 0.f);
    if (tid < B_ * NPAIR) g_S[tid] = 0.f;
    if (tid < B_ * D_)    g_mean[tid] = 0.f;
}

// ---------------- kA: y[b,d,m] += sum_{c in chunk} w[d,c]*x[b,c,m] ---------
// grid = B_*NCHUNK = 256 blocks, 224 threads (196 compute lanes, m=4 each).
// Accumulators pair over d: acc[p][m] = (y[2p], y[2p+1]) at m.
// Weights from shared are natural float2 (w[2p],w[2p+1]) -> 64 B LDS per
// c per thread (1 B/MAC crossbar, half of the duplicated-pair scheme);
// x is duplicated in-register (4 mov.b64 per c).
__global__ __launch_bounds__(224) void kA(const float* __restrict__ x,
                                          const float* __restrict__ w) {
    __shared__ __align__(16) float2 sw[CHUNK][8];  // (w[2p],w[2p+1]) per c, 16KB

    const int b   = blockIdx.x / NCHUNK;
    const int ch  = blockIdx.x % NCHUNK;
    const int c0  = ch * CHUNK;
    const int tid = threadIdx.x;

    // stage W chunk as d-pairs (no duplication)
    for (int i = tid; i < CHUNK * 8; i += 224) {
        int c = i >> 3, p = i & 7;
        sw[c][p] = make_float2(w[(2 * p)     * C_ + c0 + c],
                               w[(2 * p + 1) * C_ + c0 + c]);
    }
    __syncthreads();

    if (tid >= 196) return;             // 196*4 = 784 m positions
    const int m0 = tid * 4;
    const float* xb = x + ((size_t)b * C_ + c0) * M_ + m0;

    unsigned long long acc[8][4];
#pragma unroll
    for (int p = 0; p < 8; p++)
#pragma unroll
        for (int m = 0; m < 4; m++) acc[p][m] = 0ull;

    for (int c = 0; c < CHUNK; c += 4) {
        float4 xv[4];
#pragma unroll
        for (int u = 0; u < 4; u++)
            xv[u] = *reinterpret_cast<const float4*>(xb + (size_t)(c + u) * M_);
#pragma unroll
        for (int u = 0; u < 4; u++) {
            unsigned long long xd[4];
            xd[0] = dup2(xv[u].x);
            xd[1] = dup2(xv[u].y);
            xd[2] = dup2(xv[u].z);
            xd[3] = dup2(xv[u].w);
            const ulonglong2* wp =
                reinterpret_cast<const ulonglong2*>(&sw[c + u][0]);  // 4 x 16B
#pragma unroll
            for (int q = 0; q < 4; q++) {
                ulonglong2 w2 = wp[q];   // w2.x = pair 2q, w2.y = pair 2q+1
#pragma unroll
                for (int m = 0; m < 4; m++) {
                    fma2(acc[2 * q][m],     w2.x, xd[m]);
                    fma2(acc[2 * q + 1][m], w2.y, xd[m]);
                }
            }
        }
    }

    float* yb = g_Y + ((size_t)b * D_) * M_ + m0;
#pragma unroll
    for (int p = 0; p < 8; p++) {
#pragma unroll
        for (int m = 0; m < 4; m++) {
            float lo = __uint_as_float((unsigned int)(acc[p][m] & 0xffffffffull));
            float hi = __uint_as_float((unsigned int)(acc[p][m] >> 32));
            atomicAdd(yb + (2 * p)     * M_ + m, lo);
            atomicAdd(yb + (2 * p + 1) * M_ + m, hi);
        }
    }
}

// ---------------- kB: per-(b,d) row sums from g_Y (L2-hot, 1.6 MB) ---------
// grid = 128 blocks, 128 threads; warp w of block bid owns row bid*4+w
__global__ void kB(void) {
    const int tid = threadIdx.x;
    const int wid = tid >> 5, lane = tid & 31;
    const int row = blockIdx.x * 4 + wid;

    const float4* r4 = reinterpret_cast<const float4*>(g_Y) + row * (M_ / 4);
    float s = 0.f, s2 = 0.f;
    for (int m = lane; m < M_ / 4; m += 32) {
        float4 v = r4[m];
        s  += v.x + v.y + v.z + v.w;
        s2 += v.x * v.x + v.y * v.y + v.z * v.z + v.w * v.w;
    }
    for (int o = 16; o; o >>= 1) {
        s  += __shfl_xor_sync(~0u, s,  o);
        s2 += __shfl_xor_sync(~0u, s2, o);
    }
    if (!lane) { g_rs1[row] = s; g_rs2[row] = s2; }
}

// ---------------- kC: BN+ReLU -> partial pair sums (quarter of m) ----------
// grid = 32*4 blocks (b, m-quarter of 196), 288 threads
__global__ __launch_bounds__(288) void kC(const float* __restrict__ g1,
                                          const float* __restrict__ b1) {
    __shared__ float sS[D_], sB[D_];
    __shared__ __align__(16) float ys[D_][196];   // 12.25 KB

    const int b = blockIdx.x >> 2, qtr = blockIdx.x & 3;
    const int tid = threadIdx.x;
    const int wid = tid >> 5, lane = tid & 31;

    // BN1 coefficients (redundant per block; reads 4KB of L2-hot sums)
    if (tid < D_) {
        float s = 0.f, s2 = 0.f;
#pragma unroll
        for (int bb = 0; bb < B_; bb++) {
            s  += g_rs1[bb * D_ + tid];
            s2 += g_rs2[bb * D_ + tid];
        }
        const float inv = 1.0f / (float)(B_ * M_);
        float mu  = s * inv;
        float var = s2 * inv - mu * mu;
        float sc  = g1[tid] * rsqrtf(var + EPS);
        sS[tid] = sc;
        sB[tid] = fmaf(-mu, sc, b1[tid]);
    }
    __syncthreads();

    // stage: ys[d][0..195] = relu(bn(g_Y)) for this m-quarter (L2-hot)
    const int m4base = qtr * 49;           // float4 offset within row
    for (int idx = tid; idx < D_ * 49; idx += 288) {
        int d = idx / 49, m4 = idx % 49;
        float4 v = reinterpret_cast<const float4*>(g_Y)
                       [(b * D_ + d) * (M_ / 4) + m4base + m4];
        float sc = sS[d], bs = sB[d];
        v.x = fmaxf(fmaf(v.x, sc, bs), 0.f);
        v.y = fmaxf(fmaf(v.y, sc, bs), 0.f);
        v.z = fmaxf(fmaf(v.z, sc, bs), 0.f);
        v.w = fmaxf(fmaf(v.w, sc, bs), 0.f);
        *reinterpret_cast<float4*>(&ys[d][m4 * 4]) = v;
    }
    __syncthreads();

    // partial row sums
    for (int r = wid; r < D_; r += 9) {
        float s = 0.f;
        for (int m = lane; m < 196; m += 32) s += ys[r][m];
        for (int o = 16; o; o >>= 1) s += __shfl_xor_sync(~0u, s, o);
        if (!lane) atomicAdd(&g_mean[b * D_ + r], s);
    }

    // pair partial products: thread t -> pair t>>1, half t&1 (98 m)
    {
        int p = tid >> 1;
        bool valid = (p < NPAIR);
        int pc = valid ? p : NPAIR - 1;
        int pi = 0, rem = pc;
        while (rem >= D_ - pi) { rem -= D_ - pi; pi++; }
        int pj = pi + rem;
        int h = tid & 1;
        const float2* ri = reinterpret_cast<const float2*>(&ys[pi][h * 98]);
        const float2* rj = reinterpret_cast<const float2*>(&ys[pj][h * 98]);
        float pacc = 0.f;
#pragma unroll 7
        for (int m = 0; m < 49; m++) {
            float2 a = ri[m], c = rj[m];
            pacc = fmaf(a.x, c.x, pacc);
            pacc = fmaf(a.y, c.y, pacc);
        }
        pacc += __shfl_xor_sync(~0u, pacc, 1);
        if (valid && h == 0) atomicAdd(&g_S[b * NPAIR + p], pacc);
    }
}

// ---------------- kD: finalize cov + row-BN + row-conv -> g_r --------------
// 1 block, 512 threads (16 warps), latency-optimized
__global__ __launch_bounds__(512) void kD(const float* __restrict__ g2,
                                          const float* __restrict__ b2,
                                          const float* __restrict__ w_row) {
    __shared__ float zc[D_ * D_ * 33];     // [i][j][b'] padded, 33.8 KB
    __shared__ float smu[B_ * D_];
    __shared__ unsigned char spi[NPAIR + 4], spj[NPAIR + 4];
    __shared__ float mu2[D_], rst[D_];

    const int tid = threadIdx.x;
    const int wid = tid >> 5, lane = tid & 31;

    // pair table (decode once)
    if (tid < NPAIR) {
        int pi = 0, rem = tid;
        while (rem >= D_ - pi) { rem -= D_ - pi; pi++; }
        spi[tid] = (unsigned char)pi;
        spj[tid] = (unsigned char)(pi + rem);
    }
    if (tid < B_ * D_) smu[tid] = g_mean[tid] * (1.0f / (float)M_);
    __syncthreads();

    // finalize cov: warp w handles batches w and w+16.
    // 34 float4 groups of pairs (136/4); lanes stride so ALL groups covered.
#pragma unroll
    for (int half = 0; half < 2; half++) {
        const int bb = wid + half * 16;
        for (int gidx = lane; gidx < 34; gidx += 32) {
            float4 sv = *reinterpret_cast<const float4*>(g_S + bb * NPAIR + gidx * 4);
            float vals[4] = {sv.x, sv.y, sv.z, sv.w};
#pragma unroll
            for (int u = 0; u < 4; u++) {
                int p = gidx * 4 + u;
                int pi = spi[p], pj = spj[p];
                float cv = vals[u] * (1.0f / (float)M_)
                         - smu[bb * D_ + pi] * smu[bb * D_ + pj];
                zc[(pi * D_ + pj) * 33 + bb] = cv;
                if (pi != pj) zc[(pj * D_ + pi) * 33 + bb] = cv;
            }
        }
    }
    __syncthreads();

    // row-BN stats: warp wid owns row i = wid, reduce over (b'=lane, j)
    {
        const int i = wid;
        float s = 0.f, s2 = 0.f;
#pragma unroll
        for (int j = 0; j < D_; j++) {
            float v = zc[(i * D_ + j) * 33 + lane];
            s += v; s2 += v * v;
        }
        for (int o = 16; o; o >>= 1) {
            s  += __shfl_xor_sync(~0u, s,  o);
            s2 += __shfl_xor_sync(~0u, s2, o);
        }
        if (!lane) {
            float m   = s * (1.0f / 512.0f);
            float var = s2 * (1.0f / 512.0f) - m * m;
            mu2[i] = m;
            rst[i] = rsqrtf(var + EPS);
        }
    }
    __syncthreads();

    // grouped row conv: 2048 outputs, 4 per thread
#pragma unroll
    for (int t = tid; t < B_ * 64; t += 512) {
        int b = t >> 6, o = t & 63, g = o >> 2;
        float mg = mu2[g];
        float rg = rst[g] * g2[g];
        float bg = b2[g];
        const float* wr = w_row + o * D_;
        float a = 0.f;
#pragma unroll
        for (int h = 0; h < D_; h++) {
            float z = fmaf(zc[(g * D_ + h) * 33 + b] - mg, rg, bg);
            a = fmaf(wr[h], z, a);
        }
        g_r[t] = a;
    }
}

// ---------------- kE: FC (2048x64) + sigmoid ----------------
// grid = 32*8 blocks, 256 threads; thread -> one output channel
__global__ __launch_bounds__(256) void kE(const float* __restrict__ w_fc,
                                          float* __restrict__ out) {
    __shared__ float rs[64];
    const int b = blockIdx.x >> 3, seg = blockIdx.x & 7, tid = threadIdx.x;
    if (tid < 64) rs[tid] = g_r[b * 64 + tid];
    __syncthreads();
    const int o = seg * 256 + tid;
    const float4* wp = reinterpret_cast<const float4*>(w_fc + (size_t)o * 64);
    float acc = 0.f;
#pragma unroll
    for (int t = 0; t < 16; t++) {
        float4 wv = wp[t];
        acc += wv.x * rs[4 * t] + wv.y * rs[4 * t + 1]
             + wv.z * rs[4 * t + 2] + wv.w * rs[4 * t + 3];
    }
    out[b * C_ + o] = 1.0f / (1.0f + __expf(-acc));
}

// ---------------- launch ----------------
extern "C" void kernel_launch(void* const* d_in, const int* in_sizes, int n_in,
                              void* d_out, int out_size) {
    const float* x      = (const float*)d_in[0];
    const float* w_conv = (const float*)d_in[1];
    const float* g1     = (const float*)d_in[2];
    const float* b1     = (const float*)d_in[3];
    const float* g2     = (const float*)d_in[4];
    const float* b2     = (const float*)d_in[5];
    const float* w_row  = (const float*)d_in[6];
    const float* w_fc   = (const float*)d_in[7];
    float* out = (float*)d_out;

    kZ<<<(B_ * D_ * M_ / 4 + 255) / 256, 256>>>();
    kA<<<B_ * NCHUNK, 224>>>(x, w_conv);
    kB<<<B_ * D_ / 4, 128>>>();
    kC<<<B_ * 4, 288>>>(g1, b1);
    kD<<<1, 512>>>(g2, b2, w_row);
    kE<<<B_ * 8, 256>>>(w_fc, out);
}